// round 1
// baseline (speedup 1.0000x reference)
#include <cuda_runtime.h>
#include <cstdint>

#define R_TOT 1152
#define B_TOT 256
#define C_N 10
#define O_N 16
#define CO 160            // C_N * O_N
#define I_N 8
#define NCHUNK 8          // r-chunks per batch (1152 / 144)
#define RCHK 144          // r rows per chunk / per route block
#define TB 8              // batches per k1 block
#define CH 36             // inner r staging chunk in k1
#define PAD_STRIDE 164    // SMEM row stride (floats) for uh tile (bank-conflict pad)

// Scratch (device globals: allocation-free kernel_launch)
__device__ float g_uh[(size_t)B_TOT * R_TOT * CO];   // 189 MB, tiled [b][chunk][rin][co]
__device__ float g_b2[(size_t)B_TOT * R_TOT * C_N];  // b after iteration-1 update
__device__ float g_spart[NCHUNK * B_TOT * CO];       // deterministic partial s
__device__ float g_v[B_TOT * CO];                    // current v_j

// ---------------------------------------------------------------------------
// K1: u_hat = einsum('rcoi,bri->brco'), fused with softmax(b_init) and s1 partials.
// grid = 32 b-tiles x 8 r-chunks = 256 blocks, 160 threads (one per (c,o)).
// W row (r fixed) read once per 8 batches -> coalesced 1KB/warp from L2.
// ---------------------------------------------------------------------------
__global__ __launch_bounds__(160) void k1(const float* __restrict__ x,
                                          const float* __restrict__ W,
                                          const float* __restrict__ binit) {
    const int bt = blockIdx.x & 31;
    const int rc = blockIdx.x >> 5;          // which 144-row chunk
    const int b0 = bt * TB;
    const int tid = threadIdx.x;             // co = c*16 + o
    const int c = tid >> 4;

    __shared__ float x_sm[TB][CH][I_N];
    __shared__ float c_sm[TB][CH][C_N];

    float s_acc[TB];
#pragma unroll
    for (int i = 0; i < TB; i++) s_acc[i] = 0.f;

    const float4* W4 = reinterpret_cast<const float4*>(W);
    const float4* x4 = reinterpret_cast<const float4*>(x);

    for (int ch = 0; ch < RCHK / CH; ch++) {
        const int r0 = rc * RCHK + ch * CH;
        __syncthreads();
        // stage x tile: TB*CH*8 floats, coalesced float4
        for (int i = tid; i < TB * CH * 2; i += 160) {
            int bb = i / (CH * 2);
            int rem = i - bb * (CH * 2);
            reinterpret_cast<float4*>(&x_sm[bb][0][0])[rem] =
                x4[((size_t)(b0 + bb) * R_TOT + r0) * 2 + rem];
        }
        // softmax(b_init) for the TB*CH (b,r) pairs of this chunk
        for (int p = tid; p < TB * CH; p += 160) {
            int bb = p / CH;
            int rr = p - bb * CH;
            const float* bp = binit + ((size_t)(b0 + bb) * R_TOT + r0 + rr) * C_N;
            float e[C_N];
            float m = bp[0];
#pragma unroll
            for (int j = 1; j < C_N; j++) m = fmaxf(m, bp[j]);
            float sum = 0.f;
#pragma unroll
            for (int j = 0; j < C_N; j++) { e[j] = expf(bp[j] - m); sum += e[j]; }
            float inv = 1.f / sum;
#pragma unroll
            for (int j = 0; j < C_N; j++) c_sm[bb][rr][j] = e[j] * inv;
        }
        __syncthreads();

        for (int rr = 0; rr < CH; rr++) {
            const int r = r0 + rr;
            const float4* wp = W4 + ((size_t)r * CO + tid) * 2;   // W[r, c, o, :]
            const float4 wa = wp[0];
            const float4 wb = wp[1];
            const int rin = r - rc * RCHK;
#pragma unroll
            for (int bb = 0; bb < TB; bb++) {
                const float4* xp = reinterpret_cast<const float4*>(&x_sm[bb][rr][0]);
                float4 xa = xp[0], xb = xp[1];
                float uh = wa.x * xa.x + wa.y * xa.y + wa.z * xa.z + wa.w * xa.w
                         + wb.x * xb.x + wb.y * xb.y + wb.z * xb.z + wb.w * xb.w;
                // tiled layout: [(b*NCHUNK + rc)][rin][co]  (coalesced STG.32 per warp)
                g_uh[(((size_t)(b0 + bb) * NCHUNK + rc) * RCHK + rin) * CO + tid] = uh;
                s_acc[bb] += c_sm[bb][rr][c] * uh;
            }
        }
    }
#pragma unroll
    for (int bb = 0; bb < TB; bb++)
        g_spart[((size_t)rc * B_TOT + (b0 + bb)) * CO + tid] = s_acc[bb];
}

// ---------------------------------------------------------------------------
// squash: sum 8 deterministic s partials, v = (n/(1+n)) * s / sqrt(n+eps)
// ---------------------------------------------------------------------------
__global__ void ksquash(float* __restrict__ dout, int to_out) {
    int idx = blockIdx.x * blockDim.x + threadIdx.x;
    if (idx >= B_TOT * C_N) return;
    int b = idx / C_N;
    int cc = idx - b * C_N;
    float s[O_N];
#pragma unroll
    for (int o = 0; o < O_N; o++) s[o] = 0.f;
    for (int p = 0; p < NCHUNK; p++) {
        const float* sp = g_spart + ((size_t)p * B_TOT + b) * CO + cc * O_N;
#pragma unroll
        for (int o = 0; o < O_N; o++) s[o] += sp[o];
    }
    float norm = 0.f;
#pragma unroll
    for (int o = 0; o < O_N; o++) norm += s[o] * s[o];
    float scale = (norm / (1.f + norm)) * rsqrtf(norm + 1e-8f);
    float* dst = to_out ? dout : g_v;
    const int base = b * CO + cc * O_N;
#pragma unroll
    for (int o = 0; o < O_N; o++) dst[base + o] = scale * s[o];
}

// ---------------------------------------------------------------------------
// Fused routing pass: agreement(v_prev) -> b update -> softmax -> partial s_next.
// One 144x160 uh tile per block, staged in SMEM (read from DRAM exactly once).
// grid = 256 b x 8 chunks = 2048 blocks, 160 threads. 101.5KB dyn SMEM -> 2 blk/SM.
// ---------------------------------------------------------------------------
__global__ __launch_bounds__(160) void kroute(const float* __restrict__ binit, int first) {
    extern __shared__ float sm[];
    float* uh_sm = sm;                          // RCHK * PAD_STRIDE
    float* c_smT = sm + RCHK * PAD_STRIDE;      // [C_N][160] transposed coefficients
    float* v_sm  = c_smT + C_N * 160;           // 160

    const int b = blockIdx.x >> 3;
    const int chk = blockIdx.x & 7;
    const int tid = threadIdx.x;

    v_sm[tid] = g_v[b * CO + tid];

    // stage uh tile (coalesced float4; pad rows to 164 floats in SMEM)
    const float4* src = reinterpret_cast<const float4*>(g_uh) +
                        ((size_t)b * NCHUNK + chk) * RCHK * (CO / 4);
    for (int i = tid; i < RCHK * (CO / 4); i += 160) {
        int r = i / (CO / 4);
        int q = i - r * (CO / 4);
        *reinterpret_cast<float4*>(uh_sm + r * PAD_STRIDE + q * 4) = src[i];
    }
    __syncthreads();

    // Phase A: per-row agreement + b update + softmax (threads 0..143 = rows)
    if (tid < RCHK) {
        const int r = chk * RCHK + tid;
        const float* bin = first ? (binit + ((size_t)b * R_TOT + r) * C_N)
                                 : (g_b2 + ((size_t)b * R_TOT + r) * C_N);
        const float* urow = uh_sm + tid * PAD_STRIDE;
        float bv[C_N];
#pragma unroll
        for (int cc = 0; cc < C_N; cc++) {
            float agree = 0.f;
#pragma unroll
            for (int o = 0; o < O_N; o++)
                agree = fmaf(urow[cc * O_N + o], v_sm[cc * O_N + o], agree);
            bv[cc] = bin[cc] + agree;
        }
        if (first) {  // persist b2 for iteration 3
            float* bo = g_b2 + ((size_t)b * R_TOT + r) * C_N;
#pragma unroll
            for (int cc = 0; cc < C_N; cc++) bo[cc] = bv[cc];
        }
        float m = bv[0];
#pragma unroll
        for (int cc = 1; cc < C_N; cc++) m = fmaxf(m, bv[cc]);
        float sum = 0.f;
        float e[C_N];
#pragma unroll
        for (int cc = 0; cc < C_N; cc++) { e[cc] = expf(bv[cc] - m); sum += e[cc]; }
        float inv = 1.f / sum;
#pragma unroll
        for (int cc = 0; cc < C_N; cc++) c_smT[cc * 160 + tid] = e[cc] * inv;
    }
    __syncthreads();

    // Phase B: s partial; thread = (c,o), loop rows (conflict-free column reads)
    {
        const int cc = tid >> 4;
        const float* crow = c_smT + cc * 160;
        float s = 0.f;
        for (int r = 0; r < RCHK; r++)
            s = fmaf(crow[r], uh_sm[r * PAD_STRIDE + tid], s);
        g_spart[((size_t)chk * B_TOT + b) * CO + tid] = s;
    }
}

// ---------------------------------------------------------------------------
extern "C" void kernel_launch(void* const* d_in, const int* in_sizes, int n_in,
                              void* d_out, int out_size) {
    // identify inputs by element count (robust to ordering)
    const float *x = nullptr, *W = nullptr, *binit = nullptr;
    for (int i = 0; i < n_in; i++) {
        if (in_sizes[i] == B_TOT * R_TOT * I_N)      x     = (const float*)d_in[i];
        else if (in_sizes[i] == R_TOT * C_N * O_N * I_N) W = (const float*)d_in[i];
        else if (in_sizes[i] == B_TOT * R_TOT * C_N) binit = (const float*)d_in[i];
    }
    float* out = (float*)d_out;

    const int SMEM_ROUTE = (RCHK * PAD_STRIDE + C_N * 160 + 160) * (int)sizeof(float);
    cudaFuncSetAttribute(kroute, cudaFuncAttributeMaxDynamicSharedMemorySize, SMEM_ROUTE);

    // iter 1: u_hat + s1
    k1<<<256, 160>>>(x, W, binit);
    ksquash<<<10, 256>>>(out, 0);                       // v1
    // iter 2: agreement(v1) + b2 + softmax + s2
    kroute<<<2048, 160, SMEM_ROUTE>>>(binit, 1);
    ksquash<<<10, 256>>>(out, 0);                       // v2
    // iter 3: agreement(v2) + softmax + s3 (final b update dead -> skipped)
    kroute<<<2048, 160, SMEM_ROUTE>>>(binit, 0);
    ksquash<<<10, 256>>>(out, 1);                       // v3 -> d_out
}

// round 2
// speedup vs baseline: 1.8074x; 1.8074x over previous
#include <cuda_runtime.h>
#include <cstdint>

#define R_TOT 1152
#define B_TOT 256
#define C_N 10
#define O_N 16
#define CO 160            // C_N * O_N
#define I_N 8
#define NCHUNK 16         // r-chunks per batch
#define RCHK 72           // rows per chunk (1152/16)
#define TB 8              // batches per k1 block
#define CH 36             // inner r staging chunk in k1
#define PAD 165           // padded row stride (floats): odd -> conflict-free
#define TILE_FLOATS (RCHK * PAD)          // 11880
#define TILE_BYTES  (TILE_FLOATS * 4)     // 47520 (16B-aligned)

// Scratch (device globals: allocation-free kernel_launch)
__device__ float g_uh[(size_t)B_TOT * NCHUNK * TILE_FLOATS];   // ~195 MB, pre-padded tiles
__device__ float g_b2[(size_t)B_TOT * R_TOT * C_N];            // b after iter-1 update
__device__ float g_spart[2][NCHUNK * B_TOT * CO];              // ping-pong partial s

__device__ __forceinline__ uint32_t smem_u32(const void* p) {
    uint32_t a;
    asm("{ .reg .u64 t; cvta.to.shared.u64 t, %1; cvt.u32.u64 %0, t; }" : "=r"(a) : "l"(p));
    return a;
}

// ---------------------------------------------------------------------------
// K1: u_hat = einsum('rcoi,bri->brco'), fused softmax(b_init) + s1 partials.
// grid = 32 b-tiles x 16 chunks = 512 blocks, 160 threads (one per (c,o)).
// ---------------------------------------------------------------------------
__global__ __launch_bounds__(160) void k1(const float* __restrict__ x,
                                          const float* __restrict__ W,
                                          const float* __restrict__ binit) {
    const int bt  = blockIdx.x & 31;
    const int chk = blockIdx.x >> 5;
    const int b0  = bt * TB;
    const int tid = threadIdx.x;
    const int c   = tid >> 4;

    __shared__ float x_sm[TB][CH][I_N];
    __shared__ float c_sm[TB][CH][C_N];

    float s_acc[TB];
#pragma unroll
    for (int i = 0; i < TB; i++) s_acc[i] = 0.f;

    const float4* W4 = reinterpret_cast<const float4*>(W);
    const float4* x4 = reinterpret_cast<const float4*>(x);

    for (int ch = 0; ch < RCHK / CH; ch++) {
        const int r0 = chk * RCHK + ch * CH;
        __syncthreads();
        // stage x tile (float4-coalesced)
        for (int i = tid; i < TB * CH * 2; i += 160) {
            int bb = i / (CH * 2);
            int rem = i - bb * (CH * 2);
            reinterpret_cast<float4*>(&x_sm[bb][0][0])[rem] =
                x4[((size_t)(b0 + bb) * R_TOT + r0) * 2 + rem];
        }
        // softmax(b_init) for the TB*CH (b,r) pairs of this sub-chunk
        for (int p = tid; p < TB * CH; p += 160) {
            int bb = p / CH;
            int rr = p - bb * CH;
            const float* bp = binit + ((size_t)(b0 + bb) * R_TOT + r0 + rr) * C_N;
            float e[C_N];
            float m = bp[0];
#pragma unroll
            for (int j = 1; j < C_N; j++) m = fmaxf(m, bp[j]);
            float sum = 0.f;
#pragma unroll
            for (int j = 0; j < C_N; j++) { e[j] = expf(bp[j] - m); sum += e[j]; }
            float inv = 1.f / sum;
#pragma unroll
            for (int j = 0; j < C_N; j++) c_sm[bb][rr][j] = e[j] * inv;
        }
        __syncthreads();

        for (int rr = 0; rr < CH; rr++) {
            const int r = r0 + rr;
            const float4* wp = W4 + ((size_t)r * CO + tid) * 2;   // W[r, c, o, :]
            const float4 wa = wp[0];
            const float4 wb = wp[1];
            const int rin = ch * CH + rr;
#pragma unroll
            for (int bb = 0; bb < TB; bb++) {
                const float4* xp = reinterpret_cast<const float4*>(&x_sm[bb][rr][0]);
                float4 xa = xp[0], xb = xp[1];
                float uh = wa.x * xa.x + wa.y * xa.y + wa.z * xa.z + wa.w * xa.w
                         + wb.x * xb.x + wb.y * xb.y + wb.z * xb.z + wb.w * xb.w;
                // pre-padded tile layout: [(b*NCHUNK + chk)][rin][0..159] stride PAD
                g_uh[((size_t)(b0 + bb) * NCHUNK + chk) * TILE_FLOATS +
                     (size_t)rin * PAD + tid] = uh;
                s_acc[bb] += c_sm[bb][rr][c] * uh;
            }
        }
    }
#pragma unroll
    for (int bb = 0; bb < TB; bb++)
        g_spart[0][((size_t)chk * B_TOT + (b0 + bb)) * CO + tid] = s_acc[bb];
}

// ---------------------------------------------------------------------------
// Fused routing pass. One block per (b, chunk): bulk-copy 47.5KB uh tile,
// overlap with in-block v recompute (squash of previous s partials), then
// agreement -> b update -> softmax -> partial s_next.
// grid = 256 b x 16 chunks = 4096 blocks, 160 threads, ~51KB SMEM -> 4 blk/SM.
// ---------------------------------------------------------------------------
__global__ __launch_bounds__(160) void kroute(const float* __restrict__ binit, int iter) {
    extern __shared__ float sm[];
    float* uh = sm;                        // RCHK * PAD
    float* cT = sm + TILE_FLOATS;          // [C_N][RCHK]
    float* vs = cT + C_N * RCHK;           // CO
    __shared__ __align__(8) unsigned long long mbar;

    const int b   = blockIdx.x >> 4;
    const int chk = blockIdx.x & 15;
    const int tid = threadIdx.x;
    const int rd  = (iter == 2) ? 0 : 1;   // ping-pong spart
    const int wr  = 1 - rd;

    const uint32_t uh_s = smem_u32(uh);
    const uint32_t mb_s = smem_u32(&mbar);

    if (tid == 0) {
        asm volatile("mbarrier.init.shared.b64 [%0], 1;" :: "r"(mb_s) : "memory");
    }
    __syncthreads();
    if (tid == 0) {
        asm volatile("mbarrier.arrive.expect_tx.shared.b64 _, [%0], %1;"
                     :: "r"(mb_s), "r"((uint32_t)TILE_BYTES) : "memory");
        const float* src = g_uh + ((size_t)b * NCHUNK + chk) * TILE_FLOATS;
        asm volatile("cp.async.bulk.shared::cta.global.mbarrier::complete_tx::bytes "
                     "[%0], [%1], %2, [%3];"
                     :: "r"(uh_s), "l"(src), "r"((uint32_t)TILE_BYTES), "r"(mb_s)
                     : "memory");
    }

    // Overlap: recompute v = squash(sum of prev partials). Deterministic.
    {
        float s = 0.f;
#pragma unroll
        for (int p = 0; p < NCHUNK; p++)
            s += g_spart[rd][((size_t)p * B_TOT + b) * CO + tid];
        float n = s * s;
#pragma unroll
        for (int off = 8; off >= 1; off >>= 1)
            n += __shfl_xor_sync(0xffffffffu, n, off);
        float scale = (n / (1.f + n)) * rsqrtf(n + 1e-8f);
        vs[tid] = scale * s;
    }
    __syncthreads();

    // wait for TMA tile (phase 0)
    {
        asm volatile(
            "{\n\t.reg .pred P;\n\t"
            "W_%=: mbarrier.try_wait.parity.shared.b64 P, [%0], 0;\n\t"
            "@!P bra W_%=;\n\t}"
            :: "r"(mb_s) : "memory");
    }

    // Phase A: agreement + b update + softmax. 2 threads per row (5 caps each).
    const unsigned mask = __ballot_sync(0xffffffffu, tid < 2 * RCHK);
    if (tid < 2 * RCHK) {
        const int row = tid >> 1;
        const int c0  = (tid & 1) * 5;
        const int r   = chk * RCHK + row;
        const float* bin = (iter == 2) ? (binit + ((size_t)b * R_TOT + r) * C_N)
                                       : (g_b2  + ((size_t)b * R_TOT + r) * C_N);
        const float* urow = uh + row * PAD;
        float bv[5];
#pragma unroll
        for (int j = 0; j < 5; j++) {
            const int cc = c0 + j;
            float a = 0.f;
#pragma unroll
            for (int o = 0; o < O_N; o++)
                a = fmaf(urow[cc * O_N + o], vs[cc * O_N + o], a);
            bv[j] = bin[cc] + a;
        }
        if (iter == 2) {  // persist b2 for iteration 3
            float* bo = g_b2 + ((size_t)b * R_TOT + r) * C_N;
#pragma unroll
            for (int j = 0; j < 5; j++) bo[c0 + j] = bv[j];
        }
        float m = bv[0];
#pragma unroll
        for (int j = 1; j < 5; j++) m = fmaxf(m, bv[j]);
        m = fmaxf(m, __shfl_xor_sync(mask, m, 1));
        float e[5], ps = 0.f;
#pragma unroll
        for (int j = 0; j < 5; j++) { e[j] = expf(bv[j] - m); ps += e[j]; }
        ps += __shfl_xor_sync(mask, ps, 1);
        const float inv = 1.f / ps;
#pragma unroll
        for (int j = 0; j < 5; j++) cT[(c0 + j) * RCHK + row] = e[j] * inv;
    }
    __syncthreads();

    // Phase B: s partial; thread = (c,o), loop rows (stride-1 SMEM reads)
    {
        const int cc = tid >> 4;
        const float* crow = cT + cc * RCHK;
        float acc = 0.f;
#pragma unroll 4
        for (int r = 0; r < RCHK; r++)
            acc = fmaf(crow[r], uh[r * PAD + tid], acc);
        g_spart[wr][((size_t)chk * B_TOT + b) * CO + tid] = acc;
    }
}

// ---------------------------------------------------------------------------
// Final squash -> d_out. grid=256 (b), 160 threads (co).
// ---------------------------------------------------------------------------
__global__ __launch_bounds__(160) void ksquash(float* __restrict__ out) {
    const int b = blockIdx.x;
    const int tid = threadIdx.x;
    float s = 0.f;
#pragma unroll
    for (int p = 0; p < NCHUNK; p++)
        s += g_spart[0][((size_t)p * B_TOT + b) * CO + tid];
    float n = s * s;
#pragma unroll
    for (int off = 8; off >= 1; off >>= 1)
        n += __shfl_xor_sync(0xffffffffu, n, off);
    float scale = (n / (1.f + n)) * rsqrtf(n + 1e-8f);
    out[(size_t)b * CO + tid] = scale * s;
}

// ---------------------------------------------------------------------------
extern "C" void kernel_launch(void* const* d_in, const int* in_sizes, int n_in,
                              void* d_out, int out_size) {
    const float *x = nullptr, *W = nullptr, *binit = nullptr;
    for (int i = 0; i < n_in; i++) {
        if (in_sizes[i] == B_TOT * R_TOT * I_N)          x     = (const float*)d_in[i];
        else if (in_sizes[i] == R_TOT * C_N * O_N * I_N) W     = (const float*)d_in[i];
        else if (in_sizes[i] == B_TOT * R_TOT * C_N)     binit = (const float*)d_in[i];
    }
    float* out = (float*)d_out;

    const int SMEM_ROUTE = (TILE_FLOATS + C_N * RCHK + CO) * (int)sizeof(float);
    static int configured = 0;
    cudaFuncSetAttribute(kroute, cudaFuncAttributeMaxDynamicSharedMemorySize, SMEM_ROUTE);
    (void)configured;

    // iter 1: u_hat + s1 partials (spart buf 0)
    k1<<<512, 160>>>(x, W, binit);
    // iter 2: v1 (in-block) + agreement + b2 + softmax + s2 (buf0 -> buf1)
    kroute<<<4096, 160, SMEM_ROUTE>>>(binit, 2);
    // iter 3: v2 (in-block) + agreement + softmax + s3 (buf1 -> buf0)
    kroute<<<4096, 160, SMEM_ROUTE>>>(binit, 3);
    // final squash -> out
    ksquash<<<256, 160>>>(out);
}

// round 3
// speedup vs baseline: 2.2223x; 1.2296x over previous
#include <cuda_runtime.h>
#include <cuda_fp16.h>
#include <cstdint>

#define R_TOT 1152
#define B_TOT 256
#define C_N 10
#define O_N 16
#define CO 160
#define I_N 8

// kroute tiling
#define NCH_R 8            // route chunks per batch
#define RCHK 144           // rows per route chunk
#define PAD_H 170          // fp16 row stride (340B = 85 words, odd -> conflict-free)
#define TILE_H (RCHK * PAD_H)          // 24480 halves
#define TILE_BYTES (TILE_H * 2)        // 48960 (16B multiple)

// k1 tiling
#define TB 8               // batches per k1 block
#define K1_RC 36           // rows per k1 block
#define K1_NCH 32          // 1152/36 r-chunks

// Scratch (device globals: allocation-free kernel_launch)
__device__ __half g_uh[(size_t)B_TOT * NCH_R * TILE_H];      // ~100 MB fp16 (fits L2)
__device__ float  g_b2[(size_t)B_TOT * R_TOT * C_N];         // b after iter-1 update
__device__ float  g_spart1[(size_t)K1_NCH * B_TOT * CO];     // k1 partial s (32 chunks)
__device__ float  g_spart2[2][(size_t)NCH_R * B_TOT * CO];   // kroute partial s

__device__ __forceinline__ uint32_t smem_u32(const void* p) {
    uint32_t a;
    asm("{ .reg .u64 t; cvta.to.shared.u64 t, %1; cvt.u32.u64 %0, t; }" : "=r"(a) : "l"(p));
    return a;
}

// ---------------------------------------------------------------------------
// K1: u_hat = einsum('rcoi,bri->brco') stored as fp16 tiles, fused with
// softmax(b_init) and s1 partials. grid = 32 b-tiles x 32 r-chunks = 1024
// blocks, 160 threads (one per (c,o)). High occupancy (~21KB smem, ~40 regs).
// ---------------------------------------------------------------------------
__global__ __launch_bounds__(160) void k1(const float* __restrict__ x,
                                          const float* __restrict__ W,
                                          const float* __restrict__ binit) {
    const int bt = blockIdx.x & 31;
    const int rc = blockIdx.x >> 5;          // 0..31 (36-row chunk)
    const int b0 = bt * TB;
    const int tid = threadIdx.x;             // co
    const int c = tid >> 4;
    const int r0 = rc * K1_RC;
    const int chk_g = rc >> 2;               // 144-row tile id (36*4=144)

    __shared__ float x_sm[TB][K1_RC][I_N];
    __shared__ float c_sm[TB][K1_RC][C_N];

    const float4* W4 = reinterpret_cast<const float4*>(W);
    const float4* x4 = reinterpret_cast<const float4*>(x);

    // stage x tile (float4-coalesced): TB*K1_RC*8 floats
    for (int i = tid; i < TB * K1_RC * 2; i += 160) {
        int bb = i / (K1_RC * 2);
        int rem = i - bb * (K1_RC * 2);
        reinterpret_cast<float4*>(&x_sm[bb][0][0])[rem] =
            x4[((size_t)(b0 + bb) * R_TOT + r0) * 2 + rem];
    }
    // softmax(b_init) for the TB*K1_RC (b,r) pairs
    for (int p = tid; p < TB * K1_RC; p += 160) {
        int bb = p / K1_RC;
        int rr = p - bb * K1_RC;
        const float* bp = binit + ((size_t)(b0 + bb) * R_TOT + r0 + rr) * C_N;
        float e[C_N];
        float m = bp[0];
#pragma unroll
        for (int j = 1; j < C_N; j++) m = fmaxf(m, bp[j]);
        float sum = 0.f;
#pragma unroll
        for (int j = 0; j < C_N; j++) { e[j] = expf(bp[j] - m); sum += e[j]; }
        float inv = 1.f / sum;
#pragma unroll
        for (int j = 0; j < C_N; j++) c_sm[bb][rr][j] = e[j] * inv;
    }
    __syncthreads();

    float s_acc[TB];
#pragma unroll
    for (int i = 0; i < TB; i++) s_acc[i] = 0.f;

    for (int rr = 0; rr < K1_RC; rr++) {
        const int r = r0 + rr;
        const float4* wp = W4 + ((size_t)r * CO + tid) * 2;   // W[r, c, o, :]
        const float4 wa = wp[0];
        const float4 wb = wp[1];
        const int rin = r - chk_g * RCHK;
#pragma unroll
        for (int bb = 0; bb < TB; bb++) {
            const float4* xp = reinterpret_cast<const float4*>(&x_sm[bb][rr][0]);
            float4 xa = xp[0], xb = xp[1];
            float uh = wa.x * xa.x + wa.y * xa.y + wa.z * xa.z + wa.w * xa.w
                     + wb.x * xb.x + wb.y * xb.y + wb.z * xb.z + wb.w * xb.w;
            g_uh[((size_t)(b0 + bb) * NCH_R + chk_g) * TILE_H +
                 (size_t)rin * PAD_H + tid] = __float2half_rn(uh);
            s_acc[bb] += c_sm[bb][rr][c] * uh;
        }
    }
#pragma unroll
    for (int bb = 0; bb < TB; bb++)
        g_spart1[((size_t)rc * B_TOT + (b0 + bb)) * CO + tid] = s_acc[bb];
}

// ---------------------------------------------------------------------------
// Fused routing pass (iter = 2 or 3). One block per (b, chunk): bulk-copy
// 48.96KB fp16 uh tile (mostly L2-resident), overlap with in-block v
// recompute, then agreement -> b update -> softmax -> partial s_next.
// grid = 256 b x 8 chunks = 2048 blocks, 160 threads, ~55KB SMEM -> 4 blk/SM.
// ---------------------------------------------------------------------------
__global__ __launch_bounds__(160) void kroute(const float* __restrict__ binit, int iter) {
    extern __shared__ __align__(16) char smem_raw[];
    __half* uh = reinterpret_cast<__half*>(smem_raw);            // TILE_H halves
    float* cT  = reinterpret_cast<float*>(smem_raw + TILE_BYTES); // [C_N][RCHK]
    float* vs  = cT + C_N * RCHK;                                 // CO
    __shared__ __align__(8) unsigned long long mbar;

    const int b   = blockIdx.x >> 3;
    const int chk = blockIdx.x & 7;
    const int tid = threadIdx.x;

    const uint32_t uh_s = smem_u32(uh);
    const uint32_t mb_s = smem_u32(&mbar);

    if (tid == 0) {
        asm volatile("mbarrier.init.shared.b64 [%0], 1;" :: "r"(mb_s) : "memory");
    }
    __syncthreads();
    if (tid == 0) {
        asm volatile("mbarrier.arrive.expect_tx.shared.b64 _, [%0], %1;"
                     :: "r"(mb_s), "r"((uint32_t)TILE_BYTES) : "memory");
        const __half* src = g_uh + ((size_t)b * NCH_R + chk) * TILE_H;
        asm volatile("cp.async.bulk.shared::cta.global.mbarrier::complete_tx::bytes "
                     "[%0], [%1], %2, [%3];"
                     :: "r"(uh_s), "l"(src), "r"((uint32_t)TILE_BYTES), "r"(mb_s)
                     : "memory");
    }

    // Overlap with TMA: recompute v = squash(sum of prev partials). Deterministic.
    {
        float s = 0.f;
        if (iter == 2) {
#pragma unroll
            for (int p = 0; p < K1_NCH; p++)
                s += g_spart1[((size_t)p * B_TOT + b) * CO + tid];
        } else {
#pragma unroll
            for (int p = 0; p < NCH_R; p++)
                s += g_spart2[0][((size_t)p * B_TOT + b) * CO + tid];
        }
        float n = s * s;
#pragma unroll
        for (int off = 8; off >= 1; off >>= 1)
            n += __shfl_xor_sync(0xffffffffu, n, off);
        float scale = (n / (1.f + n)) * rsqrtf(n + 1e-8f);
        vs[tid] = scale * s;
    }
    __syncthreads();

    // wait for bulk copy (phase 0)
    asm volatile(
        "{\n\t.reg .pred P;\n\t"
        "W_%=: mbarrier.try_wait.parity.shared.b64 P, [%0], 0;\n\t"
        "@!P bra W_%=;\n\t}"
        :: "r"(mb_s) : "memory");

    // Phase A: agreement + b update + softmax. 1 thread per row.
    if (tid < RCHK) {
        const int r = chk * RCHK + tid;
        const float* bin = (iter == 2) ? (binit + ((size_t)b * R_TOT + r) * C_N)
                                       : (g_b2  + ((size_t)b * R_TOT + r) * C_N);
        const __half2* urow = reinterpret_cast<const __half2*>(uh + tid * PAD_H);
        float bv[C_N];
#pragma unroll
        for (int cc = 0; cc < C_N; cc++) {
            float a = 0.f;
#pragma unroll
            for (int k = 0; k < 8; k++) {
                float2 f = __half22float2(urow[cc * 8 + k]);
                a = fmaf(f.x, vs[cc * 16 + 2 * k], a);
                a = fmaf(f.y, vs[cc * 16 + 2 * k + 1], a);
            }
            bv[cc] = bin[cc] + a;
        }
        if (iter == 2) {  // persist b2 for iteration 3
            float* bo = g_b2 + ((size_t)b * R_TOT + r) * C_N;
#pragma unroll
            for (int cc = 0; cc < C_N; cc++) bo[cc] = bv[cc];
        }
        float m = bv[0];
#pragma unroll
        for (int cc = 1; cc < C_N; cc++) m = fmaxf(m, bv[cc]);
        float e[C_N], sum = 0.f;
#pragma unroll
        for (int cc = 0; cc < C_N; cc++) { e[cc] = expf(bv[cc] - m); sum += e[cc]; }
        float inv = 1.f / sum;
#pragma unroll
        for (int cc = 0; cc < C_N; cc++) cT[cc * RCHK + tid] = e[cc] * inv;
    }
    __syncthreads();

    // Phase B: s partial; thread = (c,o), loop rows.
    {
        const int cc = tid >> 4;
        const float* crow = cT + cc * RCHK;
        float acc = 0.f;
#pragma unroll 4
        for (int r = 0; r < RCHK; r++)
            acc = fmaf(crow[r], __half2float(uh[r * PAD_H + tid]), acc);
        const int slot = (iter == 2) ? 0 : 1;
        g_spart2[slot][((size_t)chk * B_TOT + b) * CO + tid] = acc;
    }
}

// ---------------------------------------------------------------------------
// Final squash of iter-3 partials -> d_out. grid=256 (b), 160 threads (co).
// ---------------------------------------------------------------------------
__global__ __launch_bounds__(160) void ksquash(float* __restrict__ out) {
    const int b = blockIdx.x;
    const int tid = threadIdx.x;
    float s = 0.f;
#pragma unroll
    for (int p = 0; p < NCH_R; p++)
        s += g_spart2[1][((size_t)p * B_TOT + b) * CO + tid];
    float n = s * s;
#pragma unroll
    for (int off = 8; off >= 1; off >>= 1)
        n += __shfl_xor_sync(0xffffffffu, n, off);
    float scale = (n / (1.f + n)) * rsqrtf(n + 1e-8f);
    out[(size_t)b * CO + tid] = scale * s;
}

// ---------------------------------------------------------------------------
extern "C" void kernel_launch(void* const* d_in, const int* in_sizes, int n_in,
                              void* d_out, int out_size) {
    const float *x = nullptr, *W = nullptr, *binit = nullptr;
    for (int i = 0; i < n_in; i++) {
        if (in_sizes[i] == B_TOT * R_TOT * I_N)          x     = (const float*)d_in[i];
        else if (in_sizes[i] == R_TOT * C_N * O_N * I_N) W     = (const float*)d_in[i];
        else if (in_sizes[i] == B_TOT * R_TOT * C_N)     binit = (const float*)d_in[i];
    }
    float* out = (float*)d_out;

    const int SMEM_ROUTE = TILE_BYTES + (C_N * RCHK + CO) * (int)sizeof(float);
    cudaFuncSetAttribute(kroute, cudaFuncAttributeMaxDynamicSharedMemorySize, SMEM_ROUTE);

    // iter 1: u_hat (fp16) + s1 partials
    k1<<<1024, 160>>>(x, W, binit);
    // iter 2: v1 (in-block) + agreement + b2 + softmax + s2
    kroute<<<2048, 160, SMEM_ROUTE>>>(binit, 2);
    // iter 3: v2 (in-block) + agreement + softmax + s3
    kroute<<<2048, 160, SMEM_ROUTE>>>(binit, 3);
    // final squash -> out
    ksquash<<<256, 160>>>(out);
}